// round 8
// baseline (speedup 1.0000x reference)
#include <cuda_runtime.h>
#include <cuda_bf16.h>
#include <cstdint>

#define BB    4
#define CC    64
#define HWN   16384
#define NHEAD 8
#define DD    72
#define PART  16

// ---- scratch (static __device__, no allocation) ----
__device__ unsigned g_qhl[BB*CC*HWN];   // bf16 hi (low16) | lo (high16)
__device__ unsigned g_khl[BB*CC*HWN];
__device__ unsigned g_vhl[BB*CC*HWN];
__device__ float g_kv[BB*NHEAD*DD*DD];
__device__ float g_ksum[BB*NHEAD*DD];
__device__ float g_o[BB*576*HWN];
__device__ unsigned g_y1hl[BB*CC*HWN];  // folded/counts, packed hi/lo
__device__ unsigned g_wthl[9*CC*CC];    // proj weights packed [slot][o][c]

__device__ __forceinline__ unsigned pack_hl(float v) {
    __nv_bfloat16 h = __float2bfloat16(v);
    float lf = v - __bfloat162float(h);
    __nv_bfloat16 l = __float2bfloat16(lf);
    return (unsigned)__bfloat16_as_ushort(h) | ((unsigned)__bfloat16_as_ushort(l) << 16);
}

// m16n8k16 bf16 mma, fp32 accum. A row-major, B col-major.
__device__ __forceinline__ void mma16816(float* c, const unsigned* a, const unsigned* b) {
    asm volatile(
        "mma.sync.aligned.m16n8k16.row.col.f32.bf16.bf16.f32 "
        "{%0,%1,%2,%3}, {%4,%5,%6,%7}, {%8,%9}, {%0,%1,%2,%3};"
        : "+f"(c[0]), "+f"(c[1]), "+f"(c[2]), "+f"(c[3])
        : "r"(a[0]), "r"(a[1]), "r"(a[2]), "r"(a[3]), "r"(b[0]), "r"(b[1]));
}

__device__ __forceinline__ uint32_t sptr(const void* p) {
    return (uint32_t)__cvta_generic_to_shared(p);
}
__device__ __forceinline__ void ldm4(unsigned* r, uint32_t a) {
    asm volatile("ldmatrix.sync.aligned.m8n8.x4.shared.b16 {%0,%1,%2,%3}, [%4];"
        : "=r"(r[0]), "=r"(r[1]), "=r"(r[2]), "=r"(r[3]) : "r"(a));
}
__device__ __forceinline__ void ldm2(unsigned* r, uint32_t a) {
    asm volatile("ldmatrix.sync.aligned.m8n8.x2.shared.b16 {%0,%1}, [%2];"
        : "=r"(r[0]), "=r"(r[1]) : "r"(a));
}
__device__ __forceinline__ void ldm4t(unsigned* r, uint32_t a) {
    asm volatile("ldmatrix.sync.aligned.m8n8.x4.trans.shared.b16 {%0,%1,%2,%3}, [%4];"
        : "=r"(r[0]), "=r"(r[1]), "=r"(r[2]), "=r"(r[3]) : "r"(a));
}

// ============================================================
// Kernel A: qkv 1x1 conv + bias + relu(q,k) -> packed bf16 hi/lo
// ============================================================
__global__ void qkv_kernel(const float* __restrict__ x,
                           const float* __restrict__ w,
                           const float* __restrict__ bias) {
    __shared__ float xs[32*32];
    __shared__ float ws[32*192];
    int b  = blockIdx.x >> 9;
    int n0 = (blockIdx.x & 511) << 5;
    int tid = threadIdx.x;
    int px = tid & 31;
    int og = tid >> 5;
    int obase = og * 24;
    float acc[24];
#pragma unroll
    for (int i = 0; i < 24; i++) acc[i] = 0.f;

    for (int ch = 0; ch < 2; ch++) {
        int c0 = ch * 32;
        for (int idx = tid; idx < 32*192; idx += 256) {
            int cc = idx / 192, o = idx - cc*192;
            ws[idx] = w[o*64 + c0 + cc];
        }
        for (int idx = tid; idx < 1024; idx += 256) {
            int cc = idx >> 5, p = idx & 31;
            xs[idx] = x[(b*64 + c0 + cc)*HWN + n0 + p];
        }
        __syncthreads();
#pragma unroll 8
        for (int cc = 0; cc < 32; cc++) {
            float xv = xs[cc*32 + px];
            const float4* wr = (const float4*)&ws[cc*192 + obase];
#pragma unroll
            for (int k = 0; k < 6; k++) {
                float4 w4 = wr[k];
                acc[k*4+0] += xv * w4.x;
                acc[k*4+1] += xv * w4.y;
                acc[k*4+2] += xv * w4.z;
                acc[k*4+3] += xv * w4.w;
            }
        }
        __syncthreads();
    }
    int n = n0 + px;
#pragma unroll
    for (int k = 0; k < 24; k++) {
        int o = obase + k;
        float val = acc[k] + bias[o];
        if (o < 64)       g_qhl[(b*64 + o      )*HWN + n] = pack_hl(fmaxf(val, 0.f));
        else if (o < 128) g_khl[(b*64 + (o-64) )*HWN + n] = pack_hl(fmaxf(val, 0.f));
        else              g_vhl[(b*64 + (o-128))*HWN + n] = pack_hl(val);
    }
}

__global__ void zero_kernel() {
    int idx = blockIdx.x*256 + threadIdx.x;
    if (idx < BB*NHEAD*DD*DD) g_kv[idx] = 0.f;
    if (idx < BB*NHEAD*DD)    g_ksum[idx] = 0.f;
}

// pack proj weights: g_wthl[slot][o][c]
__global__ void wt_kernel(const float* __restrict__ wp) {
    int idx = blockIdx.x*256 + threadIdx.x;   // < 9*4096
    int slot = idx >> 12;
    int rem  = idx & 4095;
    int o = rem >> 6, c = rem & 63;
    g_wthl[idx] = pack_hl(wp[o*576 + c*9 + slot]);
}

// ============================================================
// Kernel B (warp mma + ldmatrix): kv[d1][d2] += sum_n k[n,d1] v[n,d2].
// ksum via ones col (d2=72). Tiles [80 d][64 tok] stride 72. 320 thr.
// ============================================================
#define KVSTR 72
#define KVTHREADS 320
__global__ void kv_kernel() {
    __shared__ unsigned short ksh[80*KVSTR];
    __shared__ unsigned short ksl[80*KVSTR];
    __shared__ unsigned short vsh[80*KVSTR];
    __shared__ unsigned short vsl[80*KVSTR];

    int tid = threadIdx.x, wid = tid >> 5, lane = tid & 31;
    int bi = blockIdx.x;
    int b = bi / (NHEAD*PART);
    int h = (bi / PART) % NHEAD;
    int part = bi % PART;
    int nstart = part * (HWN/PART);       // 1024 tokens per CTA

    int mt = wid >> 1;
    int ntBase = (wid & 1)*5;

    // zero pad rows 72..79; ones row (d2=72) in vsh for ksum
    for (int idx = tid; idx < 8*64; idx += KVTHREADS) {
        int r = 72 + (idx >> 6), j = idx & 63;
        ksh[r*KVSTR + j] = 0; ksl[r*KVSTR + j] = 0;
        vsh[r*KVSTR + j] = (r == 72) ? (unsigned short)0x3F80 : (unsigned short)0;
        vsl[r*KVSTR + j] = 0;
    }

    // per-lane ldmatrix byte offsets
    int li = lane & 7;
    int arow = li + ((lane >> 3) & 1)*8;
    int acol = (lane >> 4)*8;
    uint32_t aKh = sptr(ksh), aKl = sptr(ksl), aVh = sptr(vsh), aVl = sptr(vsl);
    uint32_t aoff = (uint32_t)(((mt*16 + arow)*KVSTR + acol)*2);
    int bgrp = lane >> 3;
    uint32_t boff0 = (uint32_t)((((ntBase + (bgrp>>1))*8 + li)*KVSTR + (bgrp&1)*8)*2);
    uint32_t boff1 = boff0 + 16*KVSTR*2;
    uint32_t boff2 = (uint32_t)((((ntBase + 4)*8 + li)*KVSTR + ((lane>>3)&1)*8)*2);

    // fill mapping: thread owns d = tid>>2, quarter tq of 16 tokens
    int td = tid >> 2, tq = tid & 3;
    int cpr = td / 9, pp = td - cpr*9;
    int dy = pp/3 - 1, dx = pp - (pp/3)*3 - 1;
    int gbase = (b*64 + h*8)*HWN;
    const unsigned* kplane = g_khl + gbase + cpr*HWN;
    const unsigned* vplane = g_vhl + gbase + cpr*HWN;
    bool active = td < 72;

    float acc[5][4];
#pragma unroll
    for (int i = 0; i < 5; i++)
#pragma unroll
        for (int j = 0; j < 4; j++) acc[i][j] = 0.f;

    for (int t = 0; t < 16; t++) {
        int n0 = nstart + t*64;
        int y = n0 >> 7, x0 = n0 & 127;
        __syncthreads();
        if (active) {
            int sy = y + dy;
            bool rowok = (unsigned)sy < 128u;
            int jb = tq*16;
            int so = td*KVSTR + jb;
            int jbad = (dx < 0 && x0 == 0) ? 0 : ((dx > 0 && x0 == 64) ? 63 : -2);
            const unsigned* ks = kplane + sy*128 + x0 + dx + jb;
            const unsigned* vs2 = vplane + sy*128 + x0 + dx + jb;
            if (rowok && (jbad < jb || jbad >= jb + 16)) {
#pragma unroll
                for (int p = 0; p < 8; p++) {
                    unsigned k0 = ks[p*2], k1 = ks[p*2+1];
                    unsigned v0 = vs2[p*2], v1 = vs2[p*2+1];
                    *(unsigned*)&ksh[so+p*2] = __byte_perm(k0, k1, 0x5410);
                    *(unsigned*)&ksl[so+p*2] = __byte_perm(k0, k1, 0x7632);
                    *(unsigned*)&vsh[so+p*2] = __byte_perm(v0, v1, 0x5410);
                    *(unsigned*)&vsl[so+p*2] = __byte_perm(v0, v1, 0x7632);
                }
            } else if (rowok) {
#pragma unroll
                for (int p = 0; p < 8; p++) {
                    int j0 = jb + p*2;
                    unsigned k0 = (j0 == jbad)   ? 0u : ks[p*2];
                    unsigned k1 = (j0+1 == jbad) ? 0u : ks[p*2+1];
                    unsigned v0 = (j0 == jbad)   ? 0u : vs2[p*2];
                    unsigned v1 = (j0+1 == jbad) ? 0u : vs2[p*2+1];
                    *(unsigned*)&ksh[so+p*2] = __byte_perm(k0, k1, 0x5410);
                    *(unsigned*)&ksl[so+p*2] = __byte_perm(k0, k1, 0x7632);
                    *(unsigned*)&vsh[so+p*2] = __byte_perm(v0, v1, 0x5410);
                    *(unsigned*)&vsl[so+p*2] = __byte_perm(v0, v1, 0x7632);
                }
            } else {
#pragma unroll
                for (int p = 0; p < 8; p++) {
                    *(unsigned*)&ksh[so+p*2] = 0; *(unsigned*)&ksl[so+p*2] = 0;
                    *(unsigned*)&vsh[so+p*2] = 0; *(unsigned*)&vsl[so+p*2] = 0;
                }
            }
        }
        __syncthreads();
#pragma unroll
        for (int kk = 0; kk < 4; kk++) {
            uint32_t ko = kk*32;
            unsigned ah[4], al[4], bh[4], bl[4], sh[2], sl[2];
            ldm4(ah, aKh + aoff + ko);
            ldm4(al, aKl + aoff + ko);
            ldm4(bh, aVh + boff0 + ko);
            ldm4(bl, aVl + boff0 + ko);
            mma16816(acc[0], ah, bh);   mma16816(acc[0], al, bh);   mma16816(acc[0], ah, bl);
            mma16816(acc[1], ah, bh+2); mma16816(acc[1], al, bh+2); mma16816(acc[1], ah, bl+2);
            ldm4(bh, aVh + boff1 + ko);
            ldm4(bl, aVl + boff1 + ko);
            mma16816(acc[2], ah, bh);   mma16816(acc[2], al, bh);   mma16816(acc[2], ah, bl);
            mma16816(acc[3], ah, bh+2); mma16816(acc[3], al, bh+2); mma16816(acc[3], ah, bl+2);
            ldm2(sh, aVh + boff2 + ko);
            ldm2(sl, aVl + boff2 + ko);
            mma16816(acc[4], ah, sh);   mma16816(acc[4], al, sh);   mma16816(acc[4], ah, sl);
        }
    }

    // epilogue: atomics into g_kv / g_ksum
    int ly = lane >> 2, lx2 = (lane & 3)*2;
    int base = (b*NHEAD + h)*DD*DD;
    int r0 = mt*16 + ly, r1 = r0 + 8;
#pragma unroll
    for (int i = 0; i < 5; i++) {
        int e = (ntBase + i)*8 + lx2;
        if (r0 < 72) {
            if (e < 72)       atomicAdd(&g_kv[base + r0*DD + e], acc[i][0]);
            else if (e == 72) atomicAdd(&g_ksum[(b*NHEAD + h)*DD + r0], acc[i][0]);
            if (e + 1 < 72)   atomicAdd(&g_kv[base + r0*DD + e + 1], acc[i][1]);
        }
        if (r1 < 72) {
            if (e < 72)       atomicAdd(&g_kv[base + r1*DD + e], acc[i][2]);
            else if (e == 72) atomicAdd(&g_ksum[(b*NHEAD + h)*DD + r1], acc[i][2]);
            if (e + 1 < 72)   atomicAdd(&g_kv[base + r1*DD + e + 1], acc[i][3]);
        }
    }
}

// ============================================================
// Kernel C (warp mma + ldmatrix): out[n,e] = q_unf[n,:]@kv[:,e] / denom.
// A = q [128tok x 80d] stride 88; B = kvT+ksum [80e x 80d] stride 88.
// ============================================================
#define ATSTR 88
#define AT_QH 0
#define AT_QL (128*ATSTR*2)
#define AT_BH (2*128*ATSTR*2)
#define AT_BL (2*128*ATSTR*2 + 80*ATSTR*2)
#define AT_SMEM (2*128*ATSTR*2 + 2*80*ATSTR*2)
#define OSTR 132

__global__ void attn_kernel() {
    extern __shared__ char smem[];
    unsigned short* qh = (unsigned short*)(smem + AT_QH);
    unsigned short* ql = (unsigned short*)(smem + AT_QL);
    unsigned short* Bh = (unsigned short*)(smem + AT_BH);
    unsigned short* Bl = (unsigned short*)(smem + AT_BL);
    float* outs = (float*)smem;           // overlays q region after compute

    int tid = threadIdx.x, wid = tid >> 5, lane = tid & 31;
    int bi = blockIdx.x;
    int b = bi >> 10;
    int h = (bi >> 7) & 7;
    int n0 = (bi & 127) << 7;
    int y = n0 >> 7;

    // zero q pad cols 72..79 (kk=4 reads them) and whole B planes
    for (int idx = tid; idx < 512; idx += 256) {
        int tok = idx >> 2, word = idx & 3;
        ((unsigned*)&qh[tok*ATSTR + 72])[word] = 0;
        ((unsigned*)&ql[tok*ATSTR + 72])[word] = 0;
    }
    for (int idx = tid; idx < 80*ATSTR/2; idx += 256) {
        ((unsigned*)Bh)[idx] = 0; ((unsigned*)Bl)[idx] = 0;
    }

    // fill A: q tile [tok][d] — hoisted per-d contiguous gather
    int gbase = (b*64 + h*8)*HWN;
    for (int u = tid; u < 288; u += 256) {
        int d = u >> 2, tq = u & 3;
        int cpr = d / 9, pp = d - cpr*9;
        int dy = pp/3 - 1, dx = pp - (pp/3)*3 - 1;
        int sy = y + dy;
        bool rowok = (unsigned)sy < 128u;
        int jb = tq*32;
        int jbad = (dx < 0) ? 0 : ((dx > 0) ? 127 : -2);
        const unsigned* src = g_qhl + gbase + cpr*HWN + sy*128 + dx + jb;
        if (rowok) {
#pragma unroll 8
            for (int j = 0; j < 32; j++) {
                int tok = jb + j;
                unsigned u2 = (tok == jbad) ? 0u : src[j];
                qh[tok*ATSTR + d] = (unsigned short)(u2 & 0xFFFF);
                ql[tok*ATSTR + d] = (unsigned short)(u2 >> 16);
            }
        } else {
#pragma unroll 8
            for (int j = 0; j < 32; j++) {
                int tok = jb + j;
                qh[tok*ATSTR + d] = 0; ql[tok*ATSTR + d] = 0;
            }
        }
    }
    // fill B: rows e 0..71 from kv^T, row 72 = ksum
    int kvb = (b*NHEAD + h)*DD*DD;
    int ksb = (b*NHEAD + h)*DD;
    for (int idx = tid; idx < 73*72; idx += 256) {
        int e = idx / 72, d = idx - e*72;
        float v = (e < 72) ? g_kv[kvb + d*DD + e] : g_ksum[ksb + d];
        unsigned u2 = pack_hl(v);
        Bh[e*ATSTR + d] = (unsigned short)(u2 & 0xFFFF);
        Bl[e*ATSTR + d] = (unsigned short)(u2 >> 16);
    }
    __syncthreads();

    // per-lane ldmatrix offsets
    int li = lane & 7;
    int arow = li + ((lane >> 3) & 1)*8;
    int acol = (lane >> 4)*8;
    uint32_t aQh = sptr(qh), aQl = sptr(ql), aBh = sptr(Bh), aBl = sptr(Bl);
    uint32_t aoff = (uint32_t)(((wid*16 + arow)*ATSTR + acol)*2);
    int bgrp = lane >> 3;
    uint32_t boff = (uint32_t)(((((bgrp>>1))*8 + li)*ATSTR + (bgrp&1)*8)*2);

    float acc[10][4];
#pragma unroll
    for (int i = 0; i < 10; i++)
#pragma unroll
        for (int j = 0; j < 4; j++) acc[i][j] = 0.f;

#pragma unroll
    for (int kk = 0; kk < 5; kk++) {
        uint32_t ko = kk*32;
        unsigned ah[4], al[4];
        ldm4(ah, aQh + aoff + ko);
        ldm4(al, aQl + aoff + ko);
#pragma unroll
        for (int p = 0; p < 5; p++) {
            unsigned bh[4], bl[4];
            ldm4(bh, aBh + boff + (uint32_t)(p*16*ATSTR*2) + ko);
            ldm4(bl, aBl + boff + (uint32_t)(p*16*ATSTR*2) + ko);
            mma16816(acc[p*2],   ah, bh);   mma16816(acc[p*2],   al, bh);   mma16816(acc[p*2],   ah, bl);
            mma16816(acc[p*2+1], ah, bh+2); mma16816(acc[p*2+1], al, bh+2); mma16816(acc[p*2+1], ah, bl+2);
        }
    }

    int ly = lane >> 2, lx2 = (lane & 3)*2;
    // denominators: e=72 lives in n-tile 9 local col 0
    float den0 = __shfl_sync(0xffffffffu, acc[9][0], lane & ~3);
    float den1 = __shfl_sync(0xffffffffu, acc[9][2], lane & ~3);
    float inv0 = 1.f / (den0 + 1e-6f);
    float inv1 = 1.f / (den1 + 1e-6f);

    __syncthreads();   // tiles dead; reuse smem for output staging
    int r0 = wid*16 + ly, r1 = r0 + 8;
#pragma unroll
    for (int i = 0; i < 9; i++) {
        int e = i*8 + lx2;
        outs[e*OSTR + r0]     = acc[i][0] * inv0;
        outs[(e+1)*OSTR + r0] = acc[i][1] * inv0;
        outs[e*OSTR + r1]     = acc[i][2] * inv1;
        outs[(e+1)*OSTR + r1] = acc[i][3] * inv1;
    }
    __syncthreads();
    int ob = (b*576 + h*72)*HWN + n0;
    for (int idx = tid; idx < 72*128; idx += 256) {
        int e = idx >> 7, t = idx & 127;
        g_o[ob + e*HWN + t] = outs[e*OSTR + t];
    }
}

// ============================================================
// Kernel D: fold + divide by counts -> packed hi/lo
// ============================================================
__global__ void fold_kernel() {
    int idx = blockIdx.x*256 + threadIdx.x;
    int b = idx >> 20;
    int c = (idx >> 14) & 63;
    int n = idx & 16383;
    int Y = n >> 7, X = n & 127;
    float sum = 0.f;
    int cnt = 0;
#pragma unroll
    for (int i = 0; i < 3; i++)
#pragma unroll
        for (int j = 0; j < 3; j++) {
            int sy = Y + 1 - i, sx = X + 1 - j;
            if ((unsigned)sy < 128u && (unsigned)sx < 128u) {
                cnt++;
                sum += g_o[(b*576 + c*9 + i*3 + j)*HWN + sy*128 + sx];
            }
        }
    g_y1hl[idx] = pack_hl(sum / (float)cnt);
}

// ============================================================
// Kernel E (warp mma + ldmatrix): 3x3 proj conv + bias.
// Per CTA: one image row (128 tok), all 64 outputs. 9 slots of K=64.
// A = W [64 o x 64 c] stride 72; B = X [64 c x 128 tok] stride 136 (trans).
// ============================================================
#define CWSTR 72
#define XSTR  136
#define CV_WH 0
#define CV_WL (64*CWSTR*2)
#define CV_XH (2*64*CWSTR*2)
#define CV_XL (2*64*CWSTR*2 + 64*XSTR*2)
#define CV_SMEM (2*64*CWSTR*2 + 2*64*XSTR*2)

__global__ void conv_kernel(float* __restrict__ out,
                            const float* __restrict__ bproj) {
    extern __shared__ char smem[];
    unsigned short* Wh = (unsigned short*)(smem + CV_WH);
    unsigned short* Wl = (unsigned short*)(smem + CV_WL);
    unsigned short* Xh = (unsigned short*)(smem + CV_XH);
    unsigned short* Xl = (unsigned short*)(smem + CV_XL);
    float* outs = (float*)(smem + CV_XH);   // overlay after last slot

    int tid = threadIdx.x, wid = tid >> 5, lane = tid & 31;
    int b = blockIdx.x >> 7;
    int y = blockIdx.x & 127;

    int mt = wid >> 1;
    int ntBase = (wid & 1)*8;

    // per-lane ldmatrix offsets
    int li = lane & 7;
    int arow = li + ((lane >> 3) & 1)*8;
    int acol = (lane >> 4)*8;
    uint32_t aWh = sptr(Wh), aWl = sptr(Wl), aXh = sptr(Xh), aXl = sptr(Xl);
    uint32_t aoffW = (uint32_t)(((mt*16 + arow)*CWSTR + acol)*2);
    int bgrp = lane >> 3;
    uint32_t boffX = (uint32_t)((((bgrp&1)*8 + li)*XSTR + (ntBase + (bgrp>>1))*8)*2);

    // X fill mapping: thread owns c = tid>>2, quarter tq of 32 tokens
    int tc = tid >> 2, tq = tid & 3;
    const unsigned* xplane = g_y1hl + (b*64 + tc)*HWN;

    float acc[8][4];
#pragma unroll
    for (int i = 0; i < 8; i++)
#pragma unroll
        for (int j = 0; j < 4; j++) acc[i][j] = 0.f;

    for (int slot = 0; slot < 9; slot++) {
        int ky = slot / 3, kx = slot - ky*3;
        int dy = ky - 1, dx = kx - 1;
        __syncthreads();
        // W fill: 2048 pair-units
        for (int idx = tid; idx < 2048; idx += 256) {
            int o = idx >> 5, cp = (idx & 31)*2;
            unsigned u0 = g_wthl[slot*4096 + o*64 + cp];
            unsigned u1 = g_wthl[slot*4096 + o*64 + cp + 1];
            *(unsigned*)&Wh[o*CWSTR + cp] = __byte_perm(u0, u1, 0x5410);
            *(unsigned*)&Wl[o*CWSTR + cp] = __byte_perm(u0, u1, 0x7632);
        }
        // X fill: shifted contiguous row copy
        {
            int sy = y + dy;
            bool rowok = (unsigned)sy < 128u;
            int jb = tq*32;
            int so = tc*XSTR + jb;
            int jbad = (dx < 0) ? 0 : ((dx > 0) ? 127 : -2);
            const unsigned* src = xplane + sy*128 + dx + jb;
            if (rowok && (jbad < jb || jbad >= jb + 32)) {
#pragma unroll
                for (int p = 0; p < 16; p++) {
                    unsigned u0 = src[p*2], u1 = src[p*2+1];
                    *(unsigned*)&Xh[so+p*2] = __byte_perm(u0, u1, 0x5410);
                    *(unsigned*)&Xl[so+p*2] = __byte_perm(u0, u1, 0x7632);
                }
            } else if (rowok) {
#pragma unroll
                for (int p = 0; p < 16; p++) {
                    int j0 = jb + p*2;
                    unsigned u0 = (j0 == jbad)   ? 0u : src[p*2];
                    unsigned u1 = (j0+1 == jbad) ? 0u : src[p*2+1];
                    *(unsigned*)&Xh[so+p*2] = __byte_perm(u0, u1, 0x5410);
                    *(unsigned*)&Xl[so+p*2] = __byte_perm(u0, u1, 0x7632);
                }
            } else {
#pragma unroll
                for (int p = 0; p < 16; p++) {
                    *(unsigned*)&Xh[so+p*2] = 0; *(unsigned*)&Xl[so+p*2] = 0;
                }
            }
        }
        __syncthreads();
#pragma unroll
        for (int kk = 0; kk < 4; kk++) {
            uint32_t ko = kk*32;
            uint32_t kox = (uint32_t)(kk*16*XSTR*2);
            unsigned ah[4], al[4];
            ldm4(ah, aWh + aoffW + ko);
            ldm4(al, aWl + aoffW + ko);
#pragma unroll
            for (int p = 0; p < 4; p++) {
                unsigned bh[4], bl[4];
                ldm4t(bh, aXh + boffX + p*32 + kox);
                ldm4t(bl, aXl + boffX + p*32 + kox);
                mma16816(acc[p*2],   ah, bh);   mma16816(acc[p*2],   al, bh);   mma16816(acc[p*2],   ah, bl);
                mma16816(acc[p*2+1], ah, bh+2); mma16816(acc[p*2+1], al, bh+2); mma16816(acc[p*2+1], ah, bl+2);
            }
        }
    }

    // epilogue: stage through SMEM (overlay X), coalesced write + bias
    __syncthreads();
    int ly = lane >> 2, lx2 = (lane & 3)*2;
    int r0 = mt*16 + ly, r1 = r0 + 8;
#pragma unroll
    for (int i = 0; i < 8; i++) {
        int tok = (ntBase + i)*8 + lx2;
        outs[r0*132 + tok]     = acc[i][0];
        outs[r0*132 + tok + 1] = acc[i][1];
        outs[r1*132 + tok]     = acc[i][2];
        outs[r1*132 + tok + 1] = acc[i][3];
    }
    __syncthreads();
    int ob = b*64*HWN + y*128;
    for (int idx = tid; idx < 64*128; idx += 256) {
        int o = idx >> 7, tok = idx & 127;
        out[ob + o*HWN + tok] = outs[o*132 + tok] + bproj[o];
    }
}

// ============================================================
extern "C" void kernel_launch(void* const* d_in, const int* in_sizes, int n_in,
                              void* d_out, int out_size) {
    const float* x      = (const float*)d_in[0];
    const float* w_qkv  = (const float*)d_in[1];
    const float* b_qkv  = (const float*)d_in[2];
    const float* w_proj = (const float*)d_in[3];
    const float* b_proj = (const float*)d_in[4];
    float* out = (float*)d_out;

    cudaFuncSetAttribute(attn_kernel, cudaFuncAttributeMaxDynamicSharedMemorySize, AT_SMEM);
    cudaFuncSetAttribute(conv_kernel, cudaFuncAttributeMaxDynamicSharedMemorySize, CV_SMEM);

    qkv_kernel<<<2048, 256>>>(x, w_qkv, b_qkv);
    zero_kernel<<<648, 256>>>();
    wt_kernel<<<144, 256>>>(w_proj);
    kv_kernel<<<BB*NHEAD*PART, KVTHREADS>>>();
    attn_kernel<<<BB*NHEAD*128, 256, AT_SMEM>>>();
    fold_kernel<<<BB*CC*HWN/256, 256>>>();
    conv_kernel<<<BB*128, 256, CV_SMEM>>>(out, b_proj);
}